// round 12
// baseline (speedup 1.0000x reference)
#include <cuda_runtime.h>
#include <cuda_bf16.h>
#include <math.h>
#include <stdint.h>

#define BB 2
#define SS 4096
#define DD 128
#define HALF 64
#define TQ 32
#define KROWS (TQ + 2*HALF)   /* 160 */
#define NEG_INF_F (-1e30f)

#define S136 136               /* bf16 elems per row (272 B stride) */

// Split bf16 q/k/v produced by qkv kernel (hi + lo Dekker halves).
__device__ __nv_bfloat16 g_qh[BB*SS*DD], g_ql[BB*SS*DD];
__device__ __nv_bfloat16 g_kh[BB*SS*DD], g_kl[BB*SS*DD];
__device__ __nv_bfloat16 g_vh[BB*SS*DD], g_vl[BB*SS*DD];

__device__ __forceinline__ void mma16816(float* d, const uint32_t* a,
                                         const uint32_t* b) {
    asm volatile(
        "mma.sync.aligned.m16n8k16.row.col.f32.bf16.bf16.f32 "
        "{%0,%1,%2,%3}, {%4,%5,%6,%7}, {%8,%9}, {%0,%1,%2,%3};\n"
        : "+f"(d[0]), "+f"(d[1]), "+f"(d[2]), "+f"(d[3])
        : "r"(a[0]), "r"(a[1]), "r"(a[2]), "r"(a[3]), "r"(b[0]), "r"(b[1]));
}

__device__ __forceinline__ void ldmx2t(uint32_t& b0, uint32_t& b1, uint32_t a) {
    asm volatile("ldmatrix.sync.aligned.m8n8.x2.trans.shared.b16 {%0,%1}, [%2];"
                 : "=r"(b0), "=r"(b1) : "r"(a));
}

__device__ __forceinline__ uint32_t smem_u32(const void* p) {
    uint32_t a;
    asm("{ .reg .u64 t; cvta.to.shared.u64 t, %1; cvt.u32.u64 %0, t; }"
        : "=r"(a) : "l"(p));
    return a;
}

__device__ __forceinline__ __nv_bfloat162 split_hi2(float x, float y) {
    return __nv_bfloat162(__float2bfloat16(x), __float2bfloat16(y));
}
__device__ __forceinline__ __nv_bfloat162 split_lo2(float x, float y) {
    float hx = __bfloat162float(__float2bfloat16(x));
    float hy = __bfloat162float(__float2bfloat16(y));
    return __nv_bfloat162(__float2bfloat16(x - hx), __float2bfloat16(y - hy));
}

// ===================== QKV via mma.sync bf16 =====================
// W read row-major fp32 from global, split per-CTA (coalesced), B fragments
// via ldmatrix.trans — no separate wconv kernel, no transpose anywhere.

#define XTILE_B (64  * S136 * 2)
#define WTILE_B (128 * S136 * 2)
#define OFF_XHI 0
#define OFF_XLO (OFF_XHI + XTILE_B)
#define OFF_WHI (OFF_XLO + XTILE_B)
#define OFF_WLO (OFF_WHI + WTILE_B)
#define QKV_SMEM (OFF_WLO + WTILE_B)

__global__ void __launch_bounds__(256) qkv_mma_kernel(
    const float* __restrict__ x,
    const float* __restrict__ Wq, const float* __restrict__ bq,
    const float* __restrict__ Wk, const float* __restrict__ bk,
    const float* __restrict__ Wv, const float* __restrict__ bv)
{
    extern __shared__ char sb[];
    const uint32_t sbase = smem_u32(sb);
    const int tid  = threadIdx.x;
    const int wid  = tid >> 5;
    const int lane = tid & 31;
    const int row0 = blockIdx.x * 64;

    // ---- convert x tile: 64x128 fp32 -> hi/lo bf16, row stride S136 ----
    for (int idx = tid; idx < 64 * 32; idx += 256) {
        int r = idx >> 5, k = (idx & 31) << 2;
        float4 v = *(const float4*)(x + (size_t)(row0 + r) * DD + k);
        int off = (r * S136 + k) * 2;
        *(__nv_bfloat162*)(sb + OFF_XHI + off)     = split_hi2(v.x, v.y);
        *(__nv_bfloat162*)(sb + OFF_XHI + off + 4) = split_hi2(v.z, v.w);
        *(__nv_bfloat162*)(sb + OFF_XLO + off)     = split_lo2(v.x, v.y);
        *(__nv_bfloat162*)(sb + OFF_XLO + off + 4) = split_lo2(v.z, v.w);
    }

    const float* Wm[3]   = {Wq, Wk, Wv};
    const float* bias[3] = {bq, bk, bv};
    __nv_bfloat16* outh[3];
    __nv_bfloat16* outl[3];
    outh[0] = g_qh; outh[1] = g_kh; outh[2] = g_vh;
    outl[0] = g_ql; outl[1] = g_kl; outl[2] = g_vl;

    const int mw = wid & 1;          // M group (32 rows)
    const int nw = wid >> 1;         // N group (32 cols)
    const int ar = lane >> 2;
    const int ac = (lane & 3) << 2;

    for (int m = 0; m < 3; ++m) {
        if (m > 0) __syncthreads();

        // ---- convert W[k][n] fp32 -> hi/lo bf16 row-major (coalesced) ----
        const float* Wg = Wm[m];
        for (int idx = tid; idx < 128 * 32; idx += 256) {
            int k = idx >> 5, n = (idx & 31) << 2;
            float4 w = *(const float4*)(Wg + (size_t)k * DD + n);
            int off = (k * S136 + n) * 2;
            *(__nv_bfloat162*)(sb + OFF_WHI + off)     = split_hi2(w.x, w.y);
            *(__nv_bfloat162*)(sb + OFF_WHI + off + 4) = split_hi2(w.z, w.w);
            *(__nv_bfloat162*)(sb + OFF_WLO + off)     = split_lo2(w.x, w.y);
            *(__nv_bfloat162*)(sb + OFF_WLO + off + 4) = split_lo2(w.z, w.w);
        }
        __syncthreads();

        // ---- mma mainloop: warp tile M32 x N32, K=128 in 8 steps ----
        float acc[2][4][4];
        #pragma unroll
        for (int mt = 0; mt < 2; ++mt)
            #pragma unroll
            for (int nt = 0; nt < 4; ++nt)
                #pragma unroll
                for (int e = 0; e < 4; ++e) acc[mt][nt][e] = 0.f;

        #pragma unroll
        for (int ks = 0; ks < 8; ++ks) {
            const int kb = ks * 32;
            uint32_t ahi[2][4], alo[2][4];
            #pragma unroll
            for (int mt = 0; mt < 2; ++mt) {
                int abase = (mw * 32 + mt * 16 + ar) * 272 + kb + ac;
                ahi[mt][0] = *(const uint32_t*)(sb + OFF_XHI + abase);
                ahi[mt][1] = *(const uint32_t*)(sb + OFF_XHI + abase + 8*272);
                ahi[mt][2] = *(const uint32_t*)(sb + OFF_XHI + abase + 16);
                ahi[mt][3] = *(const uint32_t*)(sb + OFF_XHI + abase + 8*272 + 16);
                alo[mt][0] = *(const uint32_t*)(sb + OFF_XLO + abase);
                alo[mt][1] = *(const uint32_t*)(sb + OFF_XLO + abase + 8*272);
                alo[mt][2] = *(const uint32_t*)(sb + OFF_XLO + abase + 16);
                alo[mt][3] = *(const uint32_t*)(sb + OFF_XLO + abase + 8*272 + 16);
            }
            const uint32_t wrow = sbase + (ks * 16 + (lane & 15)) * 272;
            #pragma unroll
            for (int nt = 0; nt < 4; ++nt) {
                int n0 = nw * 32 + nt * 8;
                uint32_t bhi[2], blo[2];
                ldmx2t(bhi[0], bhi[1], wrow + OFF_WHI + n0 * 2);
                ldmx2t(blo[0], blo[1], wrow + OFF_WLO + n0 * 2);
                #pragma unroll
                for (int mt = 0; mt < 2; ++mt) {
                    mma16816(acc[mt][nt], ahi[mt], bhi);
                    mma16816(acc[mt][nt], ahi[mt], blo);
                    mma16816(acc[mt][nt], alo[mt], bhi);
                }
            }
        }

        // ---- epilogue: acc + bias -> split hi/lo bf16 globals ----
        const float* bp = bias[m];
        __nv_bfloat16* oh = outh[m];
        __nv_bfloat16* ol = outl[m];
        #pragma unroll
        for (int mt = 0; mt < 2; ++mt) {
            int grow = row0 + mw * 32 + mt * 16 + ar;
            #pragma unroll
            for (int nt = 0; nt < 4; ++nt) {
                int c = nw * 32 + nt * 8 + ((lane & 3) << 1);
                float2 b2 = *(const float2*)(bp + c);
                float v0x = acc[mt][nt][0] + b2.x;
                float v0y = acc[mt][nt][1] + b2.y;
                float v1x = acc[mt][nt][2] + b2.x;
                float v1y = acc[mt][nt][3] + b2.y;
                size_t o0 = (size_t)grow * DD + c;
                size_t o1 = (size_t)(grow + 8) * DD + c;
                *(__nv_bfloat162*)(oh + o0) = split_hi2(v0x, v0y);
                *(__nv_bfloat162*)(ol + o0) = split_lo2(v0x, v0y);
                *(__nv_bfloat162*)(oh + o1) = split_hi2(v1x, v1y);
                *(__nv_bfloat162*)(ol + o1) = split_lo2(v1x, v1y);
            }
        }
    }
}

// ============ attention: full-HMMA; loads are pure uint4 copies ============
// Phase-1 smem:  k_hi@0  k_lo@43520  q_hi@87040  q_lo@95744  (104448)
// Phase-2 smem (inside dead k region): v_hi@0 v_lo@21760 (80-row chunks)
//   sc@43520 (20992)  pt_hi@64512 pt_lo@75264 (10752 ea)  ws@86016

#define AT_KHI 0
#define AT_KLO 43520
#define AT_QHI 87040
#define AT_QLO 95744
#define AT_VH  0
#define AT_VL  21760
#define AT_SC  43520
#define AT_PTH 64512
#define AT_PTL 75264
#define AT_WS  86016
#define SCST 164
#define PTST 336
#define ATTN_SMEM 104448

__global__ void __launch_bounds__(256, 2) attn_kernel(float* __restrict__ outp)
{
    extern __shared__ char sb[];
    const uint32_t sbase = smem_u32(sb);
    const int tid  = threadIdx.x;
    const int wid  = tid >> 5;
    const int lane = tid & 31;
    const int blk  = blockIdx.x;
    const int b    = blk >> 7;
    const int s0   = (blk & 127) * TQ;
    const int lo   = s0 - HALF;

    const __nv_bfloat16* kh = g_kh + (size_t)b * SS * DD;
    const __nv_bfloat16* kl = g_kl + (size_t)b * SS * DD;
    const __nv_bfloat16* vh = g_vh + (size_t)b * SS * DD;
    const __nv_bfloat16* vl = g_vl + (size_t)b * SS * DD;
    const __nv_bfloat16* qh = g_qh + (size_t)b * SS * DD;
    const __nv_bfloat16* ql = g_ql + (size_t)b * SS * DD;

    // ---- copy k window (zero-fill OOB rows): 16B chunks ----
    for (int idx = tid; idx < KROWS * 16; idx += 256) {
        int r = idx >> 4, c = idx & 15;
        int g = lo + r;
        uint4 h = make_uint4(0,0,0,0), l = make_uint4(0,0,0,0);
        if ((unsigned)g < SS) {
            h = *(const uint4*)(kh + (size_t)g * DD + (c << 3));
            l = *(const uint4*)(kl + (size_t)g * DD + (c << 3));
        }
        *(uint4*)(sb + AT_KHI + r * 272 + (c << 4)) = h;
        *(uint4*)(sb + AT_KLO + r * 272 + (c << 4)) = l;
    }
    // ---- copy q tile ----
    for (int idx = tid; idx < TQ * 16; idx += 256) {
        int r = idx >> 4, c = idx & 15;
        *(uint4*)(sb + AT_QHI + r * 272 + (c << 4)) =
            *(const uint4*)(qh + (size_t)(s0 + r) * DD + (c << 3));
        *(uint4*)(sb + AT_QLO + r * 272 + (c << 4)) =
            *(const uint4*)(ql + (size_t)(s0 + r) * DD + (c << 3));
    }
    __syncthreads();

    // ---- HMMA scores ----
    const int mt = wid & 1;
    const int ng = wid >> 1;
    const int ar = lane >> 2;
    const int ac = (lane & 3) << 2;

    float sacc[5][4];
    #pragma unroll
    for (int nt = 0; nt < 5; ++nt)
        #pragma unroll
        for (int e = 0; e < 4; ++e) sacc[nt][e] = 0.f;

    #pragma unroll
    for (int ks = 0; ks < 8; ++ks) {
        const int kb = ks * 32;
        const int abase = (mt * 16 + ar) * 272 + kb + ac;
        uint32_t ahi[4], alo[4];
        ahi[0] = *(const uint32_t*)(sb + AT_QHI + abase);
        ahi[1] = *(const uint32_t*)(sb + AT_QHI + abase + 8*272);
        ahi[2] = *(const uint32_t*)(sb + AT_QHI + abase + 16);
        ahi[3] = *(const uint32_t*)(sb + AT_QHI + abase + 8*272 + 16);
        alo[0] = *(const uint32_t*)(sb + AT_QLO + abase);
        alo[1] = *(const uint32_t*)(sb + AT_QLO + abase + 8*272);
        alo[2] = *(const uint32_t*)(sb + AT_QLO + abase + 16);
        alo[3] = *(const uint32_t*)(sb + AT_QLO + abase + 8*272 + 16);
        #pragma unroll
        for (int nt = 0; nt < 5; ++nt) {
            int bbase = (ng * 40 + nt * 8 + ar) * 272 + kb + ac;
            uint32_t bhi[2], blo[2];
            bhi[0] = *(const uint32_t*)(sb + AT_KHI + bbase);
            bhi[1] = *(const uint32_t*)(sb + AT_KHI + bbase + 16);
            blo[0] = *(const uint32_t*)(sb + AT_KLO + bbase);
            blo[1] = *(const uint32_t*)(sb + AT_KLO + bbase + 16);
            mma16816(sacc[nt], ahi, bhi);
            mma16816(sacc[nt], ahi, blo);
            mma16816(sacc[nt], alo, bhi);
        }
    }
    __syncthreads();   // k/q dead

    // ---- store score fragments + copy v chunk 0 (rows lo..lo+79) ----
    {
        float* sc = (float*)(sb + AT_SC);
        #pragma unroll
        for (int nt = 0; nt < 5; ++nt) {
            int row = mt * 16 + ar;
            int col = ng * 40 + nt * 8 + ((lane & 3) << 1);
            *(float2*)(sc + row * SCST + col)       = make_float2(sacc[nt][0], sacc[nt][1]);
            *(float2*)(sc + (row + 8) * SCST + col) = make_float2(sacc[nt][2], sacc[nt][3]);
        }
    }
    for (int idx = tid; idx < 80 * 16; idx += 256) {
        int r = idx >> 4, c = idx & 15;
        int gc = min(max(lo + r, 0), SS - 1);
        *(uint4*)(sb + AT_VH + r * 272 + (c << 4)) =
            *(const uint4*)(vh + (size_t)gc * DD + (c << 3));
        *(uint4*)(sb + AT_VL + r * 272 + (c << 4)) =
            *(const uint4*)(vl + (size_t)gc * DD + (c << 3));
    }
    __syncthreads();

    // ---- softmax (registers + warp shfl) ----
    const int iqw = wid << 2;
    float acc[5][4];
    {
        const float* sc = (const float*)(sb + AT_SC);
        #pragma unroll
        for (int qi = 0; qi < 4; ++qi)
            #pragma unroll
            for (int t = 0; t < 5; ++t)
                acc[t][qi] = sc[(iqw + qi) * SCST + t * 32 + lane];
    }
    const float scale = 0.08838834764831844f;
    float* ws = (float*)(sb + AT_WS);
    #pragma unroll
    for (int qi = 0; qi < 4; ++qi) {
        int iq = iqw + qi;
        float mm = -INFINITY;
        #pragma unroll
        for (int t = 0; t < 5; ++t) {
            int r = t * 32 + lane;
            int j = r - iq;
            int g = lo + r;
            bool valid = (j >= 0) && (j <= 128) && ((unsigned)g < SS);
            acc[t][qi] = valid ? acc[t][qi] * scale : NEG_INF_F;
            mm = fmaxf(mm, acc[t][qi]);
        }
        mm = fmaxf(mm, __shfl_xor_sync(0xffffffffu, mm, 1));
        mm = fmaxf(mm, __shfl_xor_sync(0xffffffffu, mm, 2));
        mm = fmaxf(mm, __shfl_xor_sync(0xffffffffu, mm, 4));
        mm = fmaxf(mm, __shfl_xor_sync(0xffffffffu, mm, 8));
        mm = fmaxf(mm, __shfl_xor_sync(0xffffffffu, mm, 16));
        float s = 0.f;
        #pragma unroll
        for (int t = 0; t < 5; ++t) {
            float e = __expf(acc[t][qi] - mm);
            acc[t][qi] = e;
            s += e;
        }
        s += __shfl_xor_sync(0xffffffffu, s, 1);
        s += __shfl_xor_sync(0xffffffffu, s, 2);
        s += __shfl_xor_sync(0xffffffffu, s, 4);
        s += __shfl_xor_sync(0xffffffffu, s, 8);
        s += __shfl_xor_sync(0xffffffffu, s, 16);
        if (lane == 0) ws[iq] = s;
    }

    // ---- write probs split hi/lo into pt (row = query, col = key r) ----
    #pragma unroll
    for (int qi = 0; qi < 4; ++qi) {
        int rowb = (iqw + qi) * PTST;
        #pragma unroll
        for (int t = 0; t < 5; ++t) {
            float p = acc[t][qi];
            __nv_bfloat16 h = __float2bfloat16(p);
            __nv_bfloat16 l = __float2bfloat16(p - __bfloat162float(h));
            int cb = (t * 32 + lane) << 1;
            *(__nv_bfloat16*)(sb + AT_PTH + rowb + cb) = h;
            *(__nv_bfloat16*)(sb + AT_PTL + rowb + cb) = l;
        }
    }
    __syncthreads();

    // ---- P.V MMA: warp -> m16 (mt) x n32 (ng*32); B frags via ldmatrix.trans ----
    float oacc[4][4];
    #pragma unroll
    for (int nt = 0; nt < 4; ++nt)
        #pragma unroll
        for (int e = 0; e < 4; ++e) oacc[nt][e] = 0.f;

    for (int ck = 0; ck < 2; ++ck) {
        if (ck == 1) {
            __syncthreads();
            for (int idx = tid; idx < 80 * 16; idx += 256) {
                int r = idx >> 4, c = idx & 15;
                int gc = min(max(lo + 80 + r, 0), SS - 1);
                *(uint4*)(sb + AT_VH + r * 272 + (c << 4)) =
                    *(const uint4*)(vh + (size_t)gc * DD + (c << 3));
                *(uint4*)(sb + AT_VL + r * 272 + (c << 4)) =
                    *(const uint4*)(vl + (size_t)gc * DD + (c << 3));
            }
            __syncthreads();
        }
        const int kglob = ck * 160;
        #pragma unroll
        for (int ks = 0; ks < 5; ++ks) {
            const int abase = (mt * 16 + ar) * PTST + kglob + ks * 32 + ac;
            uint32_t phi[4], plo[4];
            phi[0] = *(const uint32_t*)(sb + AT_PTH + abase);
            phi[1] = *(const uint32_t*)(sb + AT_PTH + abase + 8*PTST);
            phi[2] = *(const uint32_t*)(sb + AT_PTH + abase + 16);
            phi[3] = *(const uint32_t*)(sb + AT_PTH + abase + 8*PTST + 16);
            plo[0] = *(const uint32_t*)(sb + AT_PTL + abase);
            plo[1] = *(const uint32_t*)(sb + AT_PTL + abase + 8*PTST);
            plo[2] = *(const uint32_t*)(sb + AT_PTL + abase + 16);
            plo[3] = *(const uint32_t*)(sb + AT_PTL + abase + 8*PTST + 16);
            const uint32_t vrow = sbase + (ks * 16 + (lane & 15)) * 272;
            #pragma unroll
            for (int nt = 0; nt < 4; ++nt) {
                int n0 = ng * 32 + nt * 8;
                uint32_t vhf[2], vlf[2];
                ldmx2t(vhf[0], vhf[1], vrow + AT_VH + n0 * 2);
                ldmx2t(vlf[0], vlf[1], vrow + AT_VL + n0 * 2);
                mma16816(oacc[nt], phi, vhf);
                mma16816(oacc[nt], phi, vlf);
                mma16816(oacc[nt], plo, vhf);
            }
        }
    }

    // ---- epilogue: normalize by ws, store ----
    {
        int q0 = mt * 16 + ar;
        float inv0 = 1.0f / ws[q0];
        float inv1 = 1.0f / ws[q0 + 8];
        float* op0 = outp + ((size_t)b * SS + s0 + q0) * DD;
        float* op1 = op0 + 8 * DD;
        #pragma unroll
        for (int nt = 0; nt < 4; ++nt) {
            int c = ng * 32 + nt * 8 + ((lane & 3) << 1);
            *(float2*)(op0 + c) = make_float2(oacc[nt][0] * inv0, oacc[nt][1] * inv0);
            *(float2*)(op1 + c) = make_float2(oacc[nt][2] * inv1, oacc[nt][3] * inv1);
        }
    }
}

extern "C" void kernel_launch(void* const* d_in, const int* in_sizes, int n_in,
                              void* d_out, int out_size)
{
    const float* x  = (const float*)d_in[0];
    const float* Wq = (const float*)d_in[1];
    const float* bq = (const float*)d_in[2];
    const float* Wk = (const float*)d_in[3];
    const float* bk = (const float*)d_in[4];
    const float* Wv = (const float*)d_in[5];
    const float* bv = (const float*)d_in[6];
    float* out = (float*)d_out;

    cudaFuncSetAttribute(qkv_mma_kernel,
                         cudaFuncAttributeMaxDynamicSharedMemorySize, QKV_SMEM);
    cudaFuncSetAttribute(attn_kernel,
                         cudaFuncAttributeMaxDynamicSharedMemorySize, ATTN_SMEM);

    qkv_mma_kernel<<<BB * SS / 64, 256, QKV_SMEM>>>(x, Wq, bq, Wk, bk, Wv, bv);
    attn_kernel<<<BB * SS / TQ, 256, ATTN_SMEM>>>(out);
}

// round 13
// speedup vs baseline: 1.1557x; 1.1557x over previous
#include <cuda_runtime.h>
#include <cuda_bf16.h>
#include <math.h>
#include <stdint.h>

#define BB 2
#define SS 4096
#define DD 128
#define HALF 64
#define TQ 32
#define KROWS (TQ + 2*HALF)   /* 160 */
#define NEG_INF_F (-1e30f)

#define S136 136               /* bf16 elems per row (272 B stride) */

// Split bf16 q/k/v produced by qkv kernel (hi + lo Dekker halves).
__device__ __nv_bfloat16 g_qh[BB*SS*DD], g_ql[BB*SS*DD];
__device__ __nv_bfloat16 g_kh[BB*SS*DD], g_kl[BB*SS*DD];
__device__ __nv_bfloat16 g_vh[BB*SS*DD], g_vl[BB*SS*DD];

// Pre-converted ROW-MAJOR W (no transpose): W[k][n] as bf16 hi/lo, stride S136.
__device__ __nv_bfloat16 g_w_hi[3][128*S136];
__device__ __nv_bfloat16 g_w_lo[3][128*S136];

__device__ __forceinline__ void mma16816(float* d, const uint32_t* a,
                                         const uint32_t* b) {
    asm volatile(
        "mma.sync.aligned.m16n8k16.row.col.f32.bf16.bf16.f32 "
        "{%0,%1,%2,%3}, {%4,%5,%6,%7}, {%8,%9}, {%0,%1,%2,%3};\n"
        : "+f"(d[0]), "+f"(d[1]), "+f"(d[2]), "+f"(d[3])
        : "r"(a[0]), "r"(a[1]), "r"(a[2]), "r"(a[3]), "r"(b[0]), "r"(b[1]));
}

__device__ __forceinline__ void ldmx2t(uint32_t& b0, uint32_t& b1, uint32_t a) {
    asm volatile("ldmatrix.sync.aligned.m8n8.x2.trans.shared.b16 {%0,%1}, [%2];"
                 : "=r"(b0), "=r"(b1) : "r"(a));
}

__device__ __forceinline__ uint32_t smem_u32(const void* p) {
    uint32_t a;
    asm("{ .reg .u64 t; cvta.to.shared.u64 t, %1; cvt.u32.u64 %0, t; }"
        : "=r"(a) : "l"(p));
    return a;
}

__device__ __forceinline__ __nv_bfloat162 split_hi2(float x, float y) {
    return __nv_bfloat162(__float2bfloat16(x), __float2bfloat16(y));
}
__device__ __forceinline__ __nv_bfloat162 split_lo2(float x, float y) {
    float hx = __bfloat162float(__float2bfloat16(x));
    float hy = __bfloat162float(__float2bfloat16(y));
    return __nv_bfloat162(__float2bfloat16(x - hx), __float2bfloat16(y - hy));
}

// ====== one-shot W convert: PURE ELEMENTWISE (no smem, no sync) ======
// 48 CTAs: (matrix, 8-row slab). Each thread converts one float4.

__global__ void __launch_bounds__(256) wconv_kernel(
    const float* __restrict__ Wq, const float* __restrict__ Wk,
    const float* __restrict__ Wv)
{
    const float* Wm[3] = {Wq, Wk, Wv};
    const float* Wg = Wm[blockIdx.x];
    __nv_bfloat16* whi = g_w_hi[blockIdx.x];
    __nv_bfloat16* wlo = g_w_lo[blockIdx.x];
    const int tid = threadIdx.x;
    const int k = blockIdx.y * 8 + (tid >> 5);   // row
    const int n = (tid & 31) << 2;               // col base

    float4 w = *(const float4*)(Wg + (size_t)k * DD + n);
    int o = k * S136 + n;
    *(__nv_bfloat162*)(whi + o)     = split_hi2(w.x, w.y);
    *(__nv_bfloat162*)(whi + o + 2) = split_hi2(w.z, w.w);
    *(__nv_bfloat162*)(wlo + o)     = split_lo2(w.x, w.y);
    *(__nv_bfloat162*)(wlo + o + 2) = split_lo2(w.z, w.w);
}

// ===================== QKV via mma.sync bf16 =====================
// W image memcpy'd row-major into smem; B fragments via ldmatrix.trans.

#define XTILE_B (64  * S136 * 2)
#define WTILE_B (128 * S136 * 2)
#define OFF_XHI 0
#define OFF_XLO (OFF_XHI + XTILE_B)
#define OFF_WHI (OFF_XLO + XTILE_B)
#define OFF_WLO (OFF_WHI + WTILE_B)
#define QKV_SMEM (OFF_WLO + WTILE_B)

__global__ void __launch_bounds__(256) qkv_mma_kernel(
    const float* __restrict__ x,
    const float* __restrict__ bq, const float* __restrict__ bk,
    const float* __restrict__ bv)
{
    extern __shared__ char sb[];
    const uint32_t sbase = smem_u32(sb);
    const int tid  = threadIdx.x;
    const int wid  = tid >> 5;
    const int lane = tid & 31;
    const int row0 = blockIdx.x * 64;

    // ---- convert x tile: 64x128 fp32 -> hi/lo bf16, row stride S136 ----
    for (int idx = tid; idx < 64 * 32; idx += 256) {
        int r = idx >> 5, k = (idx & 31) << 2;
        float4 v = *(const float4*)(x + (size_t)(row0 + r) * DD + k);
        int off = (r * S136 + k) * 2;
        *(__nv_bfloat162*)(sb + OFF_XHI + off)     = split_hi2(v.x, v.y);
        *(__nv_bfloat162*)(sb + OFF_XHI + off + 4) = split_hi2(v.z, v.w);
        *(__nv_bfloat162*)(sb + OFF_XLO + off)     = split_lo2(v.x, v.y);
        *(__nv_bfloat162*)(sb + OFF_XLO + off + 4) = split_lo2(v.z, v.w);
    }

    const float* bias[3] = {bq, bk, bv};
    __nv_bfloat16* outh[3];
    __nv_bfloat16* outl[3];
    outh[0] = g_qh; outh[1] = g_kh; outh[2] = g_vh;
    outl[0] = g_ql; outl[1] = g_kl; outl[2] = g_vl;

    const int mw = wid & 1;          // M group (32 rows)
    const int nw = wid >> 1;         // N group (32 cols)
    const int ar = lane >> 2;
    const int ac = (lane & 3) << 2;

    for (int m = 0; m < 3; ++m) {
        if (m > 0) __syncthreads();

        // ---- copy pre-converted row-major W image (pure uint4 memcpy) ----
        {
            const uint4* shi = (const uint4*)g_w_hi[m];
            const uint4* slo = (const uint4*)g_w_lo[m];
            uint4* dhi = (uint4*)(sb + OFF_WHI);
            uint4* dlo = (uint4*)(sb + OFF_WLO);
            for (int i = tid; i < WTILE_B / 16; i += 256) {
                dhi[i] = shi[i];
                dlo[i] = slo[i];
            }
        }
        __syncthreads();

        // ---- mma mainloop: warp tile M32 x N32, K=128 in 8 steps ----
        float acc[2][4][4];
        #pragma unroll
        for (int mt = 0; mt < 2; ++mt)
            #pragma unroll
            for (int nt = 0; nt < 4; ++nt)
                #pragma unroll
                for (int e = 0; e < 4; ++e) acc[mt][nt][e] = 0.f;

        #pragma unroll
        for (int ks = 0; ks < 8; ++ks) {
            const int kb = ks * 32;
            uint32_t ahi[2][4], alo[2][4];
            #pragma unroll
            for (int mt = 0; mt < 2; ++mt) {
                int abase = (mw * 32 + mt * 16 + ar) * 272 + kb + ac;
                ahi[mt][0] = *(const uint32_t*)(sb + OFF_XHI + abase);
                ahi[mt][1] = *(const uint32_t*)(sb + OFF_XHI + abase + 8*272);
                ahi[mt][2] = *(const uint32_t*)(sb + OFF_XHI + abase + 16);
                ahi[mt][3] = *(const uint32_t*)(sb + OFF_XHI + abase + 8*272 + 16);
                alo[mt][0] = *(const uint32_t*)(sb + OFF_XLO + abase);
                alo[mt][1] = *(const uint32_t*)(sb + OFF_XLO + abase + 8*272);
                alo[mt][2] = *(const uint32_t*)(sb + OFF_XLO + abase + 16);
                alo[mt][3] = *(const uint32_t*)(sb + OFF_XLO + abase + 8*272 + 16);
            }
            const uint32_t wrow = sbase + (ks * 16 + (lane & 15)) * 272;
            #pragma unroll
            for (int nt = 0; nt < 4; ++nt) {
                int n0 = nw * 32 + nt * 8;
                uint32_t bhi[2], blo[2];
                ldmx2t(bhi[0], bhi[1], wrow + OFF_WHI + n0 * 2);
                ldmx2t(blo[0], blo[1], wrow + OFF_WLO + n0 * 2);
                #pragma unroll
                for (int mt = 0; mt < 2; ++mt) {
                    mma16816(acc[mt][nt], ahi[mt], bhi);
                    mma16816(acc[mt][nt], ahi[mt], blo);
                    mma16816(acc[mt][nt], alo[mt], bhi);
                }
            }
        }

        // ---- epilogue: acc + bias -> split hi/lo bf16 globals ----
        const float* bp = bias[m];
        __nv_bfloat16* oh = outh[m];
        __nv_bfloat16* ol = outl[m];
        #pragma unroll
        for (int mt = 0; mt < 2; ++mt) {
            int grow = row0 + mw * 32 + mt * 16 + ar;
            #pragma unroll
            for (int nt = 0; nt < 4; ++nt) {
                int c = nw * 32 + nt * 8 + ((lane & 3) << 1);
                float2 b2 = *(const float2*)(bp + c);
                float v0x = acc[mt][nt][0] + b2.x;
                float v0y = acc[mt][nt][1] + b2.y;
                float v1x = acc[mt][nt][2] + b2.x;
                float v1y = acc[mt][nt][3] + b2.y;
                size_t o0 = (size_t)grow * DD + c;
                size_t o1 = (size_t)(grow + 8) * DD + c;
                *(__nv_bfloat162*)(oh + o0) = split_hi2(v0x, v0y);
                *(__nv_bfloat162*)(ol + o0) = split_lo2(v0x, v0y);
                *(__nv_bfloat162*)(oh + o1) = split_hi2(v1x, v1y);
                *(__nv_bfloat162*)(ol + o1) = split_lo2(v1x, v1y);
            }
        }
    }
}

// ============ attention: full-HMMA; loads are pure uint4 copies ============
// Phase-1 smem:  k_hi@0  k_lo@43520  q_hi@87040  q_lo@95744  (104448)
// Phase-2 smem (inside dead k region): v_hi@0 v_lo@21760 (80-row chunks)
//   sc@43520 (20992)  pt_hi@64512 pt_lo@75264 (10752 ea)  ws@86016

#define AT_KHI 0
#define AT_KLO 43520
#define AT_QHI 87040
#define AT_QLO 95744
#define AT_VH  0
#define AT_VL  21760
#define AT_SC  43520
#define AT_PTH 64512
#define AT_PTL 75264
#define AT_WS  86016
#define SCST 164
#define PTST 336
#define ATTN_SMEM 104448

__global__ void __launch_bounds__(256, 2) attn_kernel(float* __restrict__ outp)
{
    extern __shared__ char sb[];
    const uint32_t sbase = smem_u32(sb);
    const int tid  = threadIdx.x;
    const int wid  = tid >> 5;
    const int lane = tid & 31;
    const int blk  = blockIdx.x;
    const int b    = blk >> 7;
    const int s0   = (blk & 127) * TQ;
    const int lo   = s0 - HALF;

    const __nv_bfloat16* kh = g_kh + (size_t)b * SS * DD;
    const __nv_bfloat16* kl = g_kl + (size_t)b * SS * DD;
    const __nv_bfloat16* vh = g_vh + (size_t)b * SS * DD;
    const __nv_bfloat16* vl = g_vl + (size_t)b * SS * DD;
    const __nv_bfloat16* qh = g_qh + (size_t)b * SS * DD;
    const __nv_bfloat16* ql = g_ql + (size_t)b * SS * DD;

    // ---- copy k window (zero-fill OOB rows): 16B chunks ----
    for (int idx = tid; idx < KROWS * 16; idx += 256) {
        int r = idx >> 4, c = idx & 15;
        int g = lo + r;
        uint4 h = make_uint4(0,0,0,0), l = make_uint4(0,0,0,0);
        if ((unsigned)g < SS) {
            h = *(const uint4*)(kh + (size_t)g * DD + (c << 3));
            l = *(const uint4*)(kl + (size_t)g * DD + (c << 3));
        }
        *(uint4*)(sb + AT_KHI + r * 272 + (c << 4)) = h;
        *(uint4*)(sb + AT_KLO + r * 272 + (c << 4)) = l;
    }
    // ---- copy q tile ----
    for (int idx = tid; idx < TQ * 16; idx += 256) {
        int r = idx >> 4, c = idx & 15;
        *(uint4*)(sb + AT_QHI + r * 272 + (c << 4)) =
            *(const uint4*)(qh + (size_t)(s0 + r) * DD + (c << 3));
        *(uint4*)(sb + AT_QLO + r * 272 + (c << 4)) =
            *(const uint4*)(ql + (size_t)(s0 + r) * DD + (c << 3));
    }
    __syncthreads();

    // ---- HMMA scores ----
    const int mt = wid & 1;
    const int ng = wid >> 1;
    const int ar = lane >> 2;
    const int ac = (lane & 3) << 2;

    float sacc[5][4];
    #pragma unroll
    for (int nt = 0; nt < 5; ++nt)
        #pragma unroll
        for (int e = 0; e < 4; ++e) sacc[nt][e] = 0.f;

    #pragma unroll
    for (int ks = 0; ks < 8; ++ks) {
        const int kb = ks * 32;
        const int abase = (mt * 16 + ar) * 272 + kb + ac;
        uint32_t ahi[4], alo[4];
        ahi[0] = *(const uint32_t*)(sb + AT_QHI + abase);
        ahi[1] = *(const uint32_t*)(sb + AT_QHI + abase + 8*272);
        ahi[2] = *(const uint32_t*)(sb + AT_QHI + abase + 16);
        ahi[3] = *(const uint32_t*)(sb + AT_QHI + abase + 8*272 + 16);
        alo[0] = *(const uint32_t*)(sb + AT_QLO + abase);
        alo[1] = *(const uint32_t*)(sb + AT_QLO + abase + 8*272);
        alo[2] = *(const uint32_t*)(sb + AT_QLO + abase + 16);
        alo[3] = *(const uint32_t*)(sb + AT_QLO + abase + 8*272 + 16);
        #pragma unroll
        for (int nt = 0; nt < 5; ++nt) {
            int bbase = (ng * 40 + nt * 8 + ar) * 272 + kb + ac;
            uint32_t bhi[2], blo[2];
            bhi[0] = *(const uint32_t*)(sb + AT_KHI + bbase);
            bhi[1] = *(const uint32_t*)(sb + AT_KHI + bbase + 16);
            blo[0] = *(const uint32_t*)(sb + AT_KLO + bbase);
            blo[1] = *(const uint32_t*)(sb + AT_KLO + bbase + 16);
            mma16816(sacc[nt], ahi, bhi);
            mma16816(sacc[nt], ahi, blo);
            mma16816(sacc[nt], alo, bhi);
        }
    }
    __syncthreads();   // k/q dead

    // ---- store score fragments + copy v chunk 0 (rows lo..lo+79) ----
    {
        float* sc = (float*)(sb + AT_SC);
        #pragma unroll
        for (int nt = 0; nt < 5; ++nt) {
            int row = mt * 16 + ar;
            int col = ng * 40 + nt * 8 + ((lane & 3) << 1);
            *(float2*)(sc + row * SCST + col)       = make_float2(sacc[nt][0], sacc[nt][1]);
            *(float2*)(sc + (row + 8) * SCST + col) = make_float2(sacc[nt][2], sacc[nt][3]);
        }
    }
    for (int idx = tid; idx < 80 * 16; idx += 256) {
        int r = idx >> 4, c = idx & 15;
        int gc = min(max(lo + r, 0), SS - 1);
        *(uint4*)(sb + AT_VH + r * 272 + (c << 4)) =
            *(const uint4*)(vh + (size_t)gc * DD + (c << 3));
        *(uint4*)(sb + AT_VL + r * 272 + (c << 4)) =
            *(const uint4*)(vl + (size_t)gc * DD + (c << 3));
    }
    __syncthreads();

    // ---- softmax (registers + warp shfl) ----
    const int iqw = wid << 2;
    float acc[5][4];
    {
        const float* sc = (const float*)(sb + AT_SC);
        #pragma unroll
        for (int qi = 0; qi < 4; ++qi)
            #pragma unroll
            for (int t = 0; t < 5; ++t)
                acc[t][qi] = sc[(iqw + qi) * SCST + t * 32 + lane];
    }
    const float scale = 0.08838834764831844f;
    float* ws = (float*)(sb + AT_WS);
    #pragma unroll
    for (int qi = 0; qi < 4; ++qi) {
        int iq = iqw + qi;
        float mm = -INFINITY;
        #pragma unroll
        for (int t = 0; t < 5; ++t) {
            int r = t * 32 + lane;
            int j = r - iq;
            int g = lo + r;
            bool valid = (j >= 0) && (j <= 128) && ((unsigned)g < SS);
            acc[t][qi] = valid ? acc[t][qi] * scale : NEG_INF_F;
            mm = fmaxf(mm, acc[t][qi]);
        }
        mm = fmaxf(mm, __shfl_xor_sync(0xffffffffu, mm, 1));
        mm = fmaxf(mm, __shfl_xor_sync(0xffffffffu, mm, 2));
        mm = fmaxf(mm, __shfl_xor_sync(0xffffffffu, mm, 4));
        mm = fmaxf(mm, __shfl_xor_sync(0xffffffffu, mm, 8));
        mm = fmaxf(mm, __shfl_xor_sync(0xffffffffu, mm, 16));
        float s = 0.f;
        #pragma unroll
        for (int t = 0; t < 5; ++t) {
            float e = __expf(acc[t][qi] - mm);
            acc[t][qi] = e;
            s += e;
        }
        s += __shfl_xor_sync(0xffffffffu, s, 1);
        s += __shfl_xor_sync(0xffffffffu, s, 2);
        s += __shfl_xor_sync(0xffffffffu, s, 4);
        s += __shfl_xor_sync(0xffffffffu, s, 8);
        s += __shfl_xor_sync(0xffffffffu, s, 16);
        if (lane == 0) ws[iq] = s;
    }

    // ---- write probs split hi/lo into pt (row = query, col = key r) ----
    #pragma unroll
    for (int qi = 0; qi < 4; ++qi) {
        int rowb = (iqw + qi) * PTST;
        #pragma unroll
        for (int t = 0; t < 5; ++t) {
            float p = acc[t][qi];
            __nv_bfloat16 h = __float2bfloat16(p);
            __nv_bfloat16 l = __float2bfloat16(p - __bfloat162float(h));
            int cb = (t * 32 + lane) << 1;
            *(__nv_bfloat16*)(sb + AT_PTH + rowb + cb) = h;
            *(__nv_bfloat16*)(sb + AT_PTL + rowb + cb) = l;
        }
    }
    __syncthreads();

    // ---- P.V MMA: warp -> m16 (mt) x n32 (ng*32); B frags via ldmatrix.trans ----
    float oacc[4][4];
    #pragma unroll
    for (int nt = 0; nt < 4; ++nt)
        #pragma unroll
        for (int e = 0; e < 4; ++e) oacc[nt][e] = 0.f;

    for (int ck = 0; ck < 2; ++ck) {
        if (ck == 1) {
            __syncthreads();
            for (int idx = tid; idx < 80 * 16; idx += 256) {
                int r = idx >> 4, c = idx & 15;
                int gc = min(max(lo + 80 + r, 0), SS - 1);
                *(uint4*)(sb + AT_VH + r * 272 + (c << 4)) =
                    *(const uint4*)(vh + (size_t)gc * DD + (c << 3));
                *(uint4*)(sb + AT_VL + r * 272 + (c << 4)) =
                    *(const uint4*)(vl + (size_t)gc * DD + (c << 3));
            }
            __syncthreads();
        }
        const int kglob = ck * 160;
        #pragma unroll
        for (int ks = 0; ks < 5; ++ks) {
            const int abase = (mt * 16 + ar) * PTST + kglob + ks * 32 + ac;
            uint32_t phi[4], plo[4];
            phi[0] = *(const uint32_t*)(sb + AT_PTH + abase);
            phi[1] = *(const uint32_t*)(sb + AT_PTH + abase + 8*PTST);
            phi[2] = *(const uint32_t*)(sb + AT_PTH + abase + 16);
            phi[3] = *(const uint32_t*)(sb + AT_PTH + abase + 8*PTST + 16);
            plo[0] = *(const uint32_t*)(sb + AT_PTL + abase);
            plo[1] = *(const uint32_t*)(sb + AT_PTL + abase + 8*PTST);
            plo[2] = *(const uint32_t*)(sb + AT_PTL + abase + 16);
            plo[3] = *(const uint32_t*)(sb + AT_PTL + abase + 8*PTST + 16);
            const uint32_t vrow = sbase + (ks * 16 + (lane & 15)) * 272;
            #pragma unroll
            for (int nt = 0; nt < 4; ++nt) {
                int n0 = ng * 32 + nt * 8;
                uint32_t vhf[2], vlf[2];
                ldmx2t(vhf[0], vhf[1], vrow + AT_VH + n0 * 2);
                ldmx2t(vlf[0], vlf[1], vrow + AT_VL + n0 * 2);
                mma16816(oacc[nt], phi, vhf);
                mma16816(oacc[nt], phi, vlf);
                mma16816(oacc[nt], plo, vhf);
            }
        }
    }

    // ---- epilogue: normalize by ws, store ----
    {
        int q0 = mt * 16 + ar;
        float inv0 = 1.0f / ws[q0];
        float inv1 = 1.0f / ws[q0 + 8];
        float* op0 = outp + ((size_t)b * SS + s0 + q0) * DD;
        float* op1 = op0 + 8 * DD;
        #pragma unroll
        for (int nt = 0; nt < 4; ++nt) {
            int c = ng * 32 + nt * 8 + ((lane & 3) << 1);
            *(float2*)(op0 + c) = make_float2(oacc[nt][0] * inv0, oacc[nt][1] * inv0);
            *(float2*)(op1 + c) = make_float2(oacc[nt][2] * inv1, oacc[nt][3] * inv1);
        }
    }
}

extern "C" void kernel_launch(void* const* d_in, const int* in_sizes, int n_in,
                              void* d_out, int out_size)
{
    const float* x  = (const float*)d_in[0];
    const float* Wq = (const float*)d_in[1];
    const float* bq = (const float*)d_in[2];
    const float* Wk = (const float*)d_in[3];
    const float* bk = (const float*)d_in[4];
    const float* Wv = (const float*)d_in[5];
    const float* bv = (const float*)d_in[6];
    float* out = (float*)d_out;

    cudaFuncSetAttribute(qkv_mma_kernel,
                         cudaFuncAttributeMaxDynamicSharedMemorySize, QKV_SMEM);
    cudaFuncSetAttribute(attn_kernel,
                         cudaFuncAttributeMaxDynamicSharedMemorySize, ATTN_SMEM);

    wconv_kernel<<<dim3(3, 16), 256>>>(Wq, Wk, Wv);
    qkv_mma_kernel<<<BB * SS / 64, 256, QKV_SMEM>>>(x, bq, bk, bv);
    attn_kernel<<<BB * SS / TQ, 256, ATTN_SMEM>>>(out);
}

// round 14
// speedup vs baseline: 1.1750x; 1.0167x over previous
#include <cuda_runtime.h>
#include <cuda_bf16.h>
#include <math.h>
#include <stdint.h>

#define BB 2
#define SS 4096
#define DD 128
#define HALF 64
#define TQ 32
#define KROWS (TQ + 2*HALF)   /* 160 */
#define NEG_INF_F (-1e30f)

#define S136 136               /* bf16 elems per row (272 B stride) */

// Split bf16 q/k/v produced by qkv kernel (hi + lo Dekker halves).
__device__ __nv_bfloat16 g_qh[BB*SS*DD], g_ql[BB*SS*DD];
__device__ __nv_bfloat16 g_kh[BB*SS*DD], g_kl[BB*SS*DD];
__device__ __nv_bfloat16 g_vh[BB*SS*DD], g_vl[BB*SS*DD];

// Pre-converted ROW-MAJOR W (no transpose): W[k][n] as bf16 hi/lo, stride S136.
__device__ __nv_bfloat16 g_w_hi[3][128*S136];
__device__ __nv_bfloat16 g_w_lo[3][128*S136];

__device__ __forceinline__ void mma16816(float* d, const uint32_t* a,
                                         const uint32_t* b) {
    asm volatile(
        "mma.sync.aligned.m16n8k16.row.col.f32.bf16.bf16.f32 "
        "{%0,%1,%2,%3}, {%4,%5,%6,%7}, {%8,%9}, {%0,%1,%2,%3};\n"
        : "+f"(d[0]), "+f"(d[1]), "+f"(d[2]), "+f"(d[3])
        : "r"(a[0]), "r"(a[1]), "r"(a[2]), "r"(a[3]), "r"(b[0]), "r"(b[1]));
}

__device__ __forceinline__ void ldmx2t(uint32_t& b0, uint32_t& b1, uint32_t a) {
    asm volatile("ldmatrix.sync.aligned.m8n8.x2.trans.shared.b16 {%0,%1}, [%2];"
                 : "=r"(b0), "=r"(b1) : "r"(a));
}

__device__ __forceinline__ uint32_t smem_u32(const void* p) {
    uint32_t a;
    asm("{ .reg .u64 t; cvta.to.shared.u64 t, %1; cvt.u32.u64 %0, t; }"
        : "=r"(a) : "l"(p));
    return a;
}

__device__ __forceinline__ __nv_bfloat162 split_hi2(float x, float y) {
    return __nv_bfloat162(__float2bfloat16(x), __float2bfloat16(y));
}
__device__ __forceinline__ __nv_bfloat162 split_lo2(float x, float y) {
    float hx = __bfloat162float(__float2bfloat16(x));
    float hy = __bfloat162float(__float2bfloat16(y));
    return __nv_bfloat162(__float2bfloat16(x - hx), __float2bfloat16(y - hy));
}

// ====== one-shot W convert: PURE ELEMENTWISE (no smem, no sync) ======

__global__ void __launch_bounds__(256) wconv_kernel(
    const float* __restrict__ Wq, const float* __restrict__ Wk,
    const float* __restrict__ Wv)
{
    const float* Wm[3] = {Wq, Wk, Wv};
    const float* Wg = Wm[blockIdx.x];
    __nv_bfloat16* whi = g_w_hi[blockIdx.x];
    __nv_bfloat16* wlo = g_w_lo[blockIdx.x];
    const int tid = threadIdx.x;
    const int k = blockIdx.y * 8 + (tid >> 5);
    const int n = (tid & 31) << 2;

    float4 w = *(const float4*)(Wg + (size_t)k * DD + n);
    int o = k * S136 + n;
    *(__nv_bfloat162*)(whi + o)     = split_hi2(w.x, w.y);
    *(__nv_bfloat162*)(whi + o + 2) = split_hi2(w.z, w.w);
    *(__nv_bfloat162*)(wlo + o)     = split_lo2(w.x, w.y);
    *(__nv_bfloat162*)(wlo + o + 2) = split_lo2(w.z, w.w);
}

// ===================== QKV via mma.sync bf16 (unchanged R13) ==============

#define XTILE_B (64  * S136 * 2)
#define WTILE_B (128 * S136 * 2)
#define OFF_XHI 0
#define OFF_XLO (OFF_XHI + XTILE_B)
#define OFF_WHI (OFF_XLO + XTILE_B)
#define OFF_WLO (OFF_WHI + WTILE_B)
#define QKV_SMEM (OFF_WLO + WTILE_B)

__global__ void __launch_bounds__(256) qkv_mma_kernel(
    const float* __restrict__ x,
    const float* __restrict__ bq, const float* __restrict__ bk,
    const float* __restrict__ bv)
{
    extern __shared__ char sb[];
    const uint32_t sbase = smem_u32(sb);
    const int tid  = threadIdx.x;
    const int wid  = tid >> 5;
    const int lane = tid & 31;
    const int row0 = blockIdx.x * 64;

    for (int idx = tid; idx < 64 * 32; idx += 256) {
        int r = idx >> 5, k = (idx & 31) << 2;
        float4 v = *(const float4*)(x + (size_t)(row0 + r) * DD + k);
        int off = (r * S136 + k) * 2;
        *(__nv_bfloat162*)(sb + OFF_XHI + off)     = split_hi2(v.x, v.y);
        *(__nv_bfloat162*)(sb + OFF_XHI + off + 4) = split_hi2(v.z, v.w);
        *(__nv_bfloat162*)(sb + OFF_XLO + off)     = split_lo2(v.x, v.y);
        *(__nv_bfloat162*)(sb + OFF_XLO + off + 4) = split_lo2(v.z, v.w);
    }

    const float* bias[3] = {bq, bk, bv};
    __nv_bfloat16* outh[3];
    __nv_bfloat16* outl[3];
    outh[0] = g_qh; outh[1] = g_kh; outh[2] = g_vh;
    outl[0] = g_ql; outl[1] = g_kl; outl[2] = g_vl;

    const int mw = wid & 1;
    const int nw = wid >> 1;
    const int ar = lane >> 2;
    const int ac = (lane & 3) << 2;

    for (int m = 0; m < 3; ++m) {
        if (m > 0) __syncthreads();
        {
            const uint4* shi = (const uint4*)g_w_hi[m];
            const uint4* slo = (const uint4*)g_w_lo[m];
            uint4* dhi = (uint4*)(sb + OFF_WHI);
            uint4* dlo = (uint4*)(sb + OFF_WLO);
            for (int i = tid; i < WTILE_B / 16; i += 256) {
                dhi[i] = shi[i];
                dlo[i] = slo[i];
            }
        }
        __syncthreads();

        float acc[2][4][4];
        #pragma unroll
        for (int mt = 0; mt < 2; ++mt)
            #pragma unroll
            for (int nt = 0; nt < 4; ++nt)
                #pragma unroll
                for (int e = 0; e < 4; ++e) acc[mt][nt][e] = 0.f;

        #pragma unroll
        for (int ks = 0; ks < 8; ++ks) {
            const int kb = ks * 32;
            uint32_t ahi[2][4], alo[2][4];
            #pragma unroll
            for (int mt = 0; mt < 2; ++mt) {
                int abase = (mw * 32 + mt * 16 + ar) * 272 + kb + ac;
                ahi[mt][0] = *(const uint32_t*)(sb + OFF_XHI + abase);
                ahi[mt][1] = *(const uint32_t*)(sb + OFF_XHI + abase + 8*272);
                ahi[mt][2] = *(const uint32_t*)(sb + OFF_XHI + abase + 16);
                ahi[mt][3] = *(const uint32_t*)(sb + OFF_XHI + abase + 8*272 + 16);
                alo[mt][0] = *(const uint32_t*)(sb + OFF_XLO + abase);
                alo[mt][1] = *(const uint32_t*)(sb + OFF_XLO + abase + 8*272);
                alo[mt][2] = *(const uint32_t*)(sb + OFF_XLO + abase + 16);
                alo[mt][3] = *(const uint32_t*)(sb + OFF_XLO + abase + 8*272 + 16);
            }
            const uint32_t wrow = sbase + (ks * 16 + (lane & 15)) * 272;
            #pragma unroll
            for (int nt = 0; nt < 4; ++nt) {
                int n0 = nw * 32 + nt * 8;
                uint32_t bhi[2], blo[2];
                ldmx2t(bhi[0], bhi[1], wrow + OFF_WHI + n0 * 2);
                ldmx2t(blo[0], blo[1], wrow + OFF_WLO + n0 * 2);
                #pragma unroll
                for (int mt = 0; mt < 2; ++mt) {
                    mma16816(acc[mt][nt], ahi[mt], bhi);
                    mma16816(acc[mt][nt], ahi[mt], blo);
                    mma16816(acc[mt][nt], alo[mt], bhi);
                }
            }
        }

        const float* bp = bias[m];
        __nv_bfloat16* oh = outh[m];
        __nv_bfloat16* ol = outl[m];
        #pragma unroll
        for (int mt = 0; mt < 2; ++mt) {
            int grow = row0 + mw * 32 + mt * 16 + ar;
            #pragma unroll
            for (int nt = 0; nt < 4; ++nt) {
                int c = nw * 32 + nt * 8 + ((lane & 3) << 1);
                float2 b2 = *(const float2*)(bp + c);
                float v0x = acc[mt][nt][0] + b2.x;
                float v0y = acc[mt][nt][1] + b2.y;
                float v1x = acc[mt][nt][2] + b2.x;
                float v1y = acc[mt][nt][3] + b2.y;
                size_t o0 = (size_t)grow * DD + c;
                size_t o1 = (size_t)(grow + 8) * DD + c;
                *(__nv_bfloat162*)(oh + o0) = split_hi2(v0x, v0y);
                *(__nv_bfloat162*)(ol + o0) = split_lo2(v0x, v0y);
                *(__nv_bfloat162*)(oh + o1) = split_hi2(v1x, v1y);
                *(__nv_bfloat162*)(ol + o1) = split_lo2(v1x, v1y);
            }
        }
    }
}

// ===== attention: fragment-native softmax, single-phase PV =====
// Phase-1: k_hi@0 k_lo@43520 (87040) | q_hi@87040 q_lo@95744 (ends 104448)
// Phase-2: v_hi@0 v_lo@43520 (full 160 rows, over dead k)
//          pt_hi@87040 pt_lo@97792 (over dead q)
//          pmax@108544 psum@109056 ws@109568 (ends 109696)

#define AT_KHI 0
#define AT_KLO 43520
#define AT_QHI 87040
#define AT_QLO 95744
#define AT_VH   0
#define AT_VL   43520
#define AT_PTH  87040
#define AT_PTL  97792
#define AT_PMAX 108544
#define AT_PSUM 109056
#define AT_WS   109568
#define PTST 336
#define ATTN_SMEM 109696

__global__ void __launch_bounds__(256, 2) attn_kernel(float* __restrict__ outp)
{
    extern __shared__ char sb[];
    const uint32_t sbase = smem_u32(sb);
    const int tid  = threadIdx.x;
    const int wid  = tid >> 5;
    const int lane = tid & 31;
    const int blk  = blockIdx.x;
    const int b    = blk >> 7;
    const int s0   = (blk & 127) * TQ;
    const int lo   = s0 - HALF;

    const __nv_bfloat16* kh = g_kh + (size_t)b * SS * DD;
    const __nv_bfloat16* kl = g_kl + (size_t)b * SS * DD;
    const __nv_bfloat16* vh = g_vh + (size_t)b * SS * DD;
    const __nv_bfloat16* vl = g_vl + (size_t)b * SS * DD;
    const __nv_bfloat16* qh = g_qh + (size_t)b * SS * DD;
    const __nv_bfloat16* ql = g_ql + (size_t)b * SS * DD;

    // ---- copy k window (zero-fill OOB rows) + q tile ----
    for (int idx = tid; idx < KROWS * 16; idx += 256) {
        int r = idx >> 4, c = idx & 15;
        int g = lo + r;
        uint4 h = make_uint4(0,0,0,0), l = make_uint4(0,0,0,0);
        if ((unsigned)g < SS) {
            h = *(const uint4*)(kh + (size_t)g * DD + (c << 3));
            l = *(const uint4*)(kl + (size_t)g * DD + (c << 3));
        }
        *(uint4*)(sb + AT_KHI + r * 272 + (c << 4)) = h;
        *(uint4*)(sb + AT_KLO + r * 272 + (c << 4)) = l;
    }
    for (int idx = tid; idx < TQ * 16; idx += 256) {
        int r = idx >> 4, c = idx & 15;
        *(uint4*)(sb + AT_QHI + r * 272 + (c << 4)) =
            *(const uint4*)(qh + (size_t)(s0 + r) * DD + (c << 3));
        *(uint4*)(sb + AT_QLO + r * 272 + (c << 4)) =
            *(const uint4*)(ql + (size_t)(s0 + r) * DD + (c << 3));
    }
    __syncthreads();

    // ---- HMMA scores ----
    const int mt = wid & 1;
    const int ng = wid >> 1;
    const int ar = lane >> 2;
    const int ac = (lane & 3) << 2;

    float sacc[5][4];
    #pragma unroll
    for (int nt = 0; nt < 5; ++nt)
        #pragma unroll
        for (int e = 0; e < 4; ++e) sacc[nt][e] = 0.f;

    #pragma unroll
    for (int ks = 0; ks < 8; ++ks) {
        const int kb = ks * 32;
        const int abase = (mt * 16 + ar) * 272 + kb + ac;
        uint32_t ahi[4], alo[4];
        ahi[0] = *(const uint32_t*)(sb + AT_QHI + abase);
        ahi[1] = *(const uint32_t*)(sb + AT_QHI + abase + 8*272);
        ahi[2] = *(const uint32_t*)(sb + AT_QHI + abase + 16);
        ahi[3] = *(const uint32_t*)(sb + AT_QHI + abase + 8*272 + 16);
        alo[0] = *(const uint32_t*)(sb + AT_QLO + abase);
        alo[1] = *(const uint32_t*)(sb + AT_QLO + abase + 8*272);
        alo[2] = *(const uint32_t*)(sb + AT_QLO + abase + 16);
        alo[3] = *(const uint32_t*)(sb + AT_QLO + abase + 8*272 + 16);
        #pragma unroll
        for (int nt = 0; nt < 5; ++nt) {
            int bbase = (ng * 40 + nt * 8 + ar) * 272 + kb + ac;
            uint32_t bhi[2], blo[2];
            bhi[0] = *(const uint32_t*)(sb + AT_KHI + bbase);
            bhi[1] = *(const uint32_t*)(sb + AT_KHI + bbase + 16);
            blo[0] = *(const uint32_t*)(sb + AT_KLO + bbase);
            blo[1] = *(const uint32_t*)(sb + AT_KLO + bbase + 16);
            mma16816(sacc[nt], ahi, bhi);
            mma16816(sacc[nt], ahi, blo);
            mma16816(sacc[nt], alo, bhi);
        }
    }

    // ---- fragment-native mask/scale + group max/sum partials ----
    const float scale = 0.08838834764831844f;
    const int r0 = mt * 16 + ar;        // local q row (elems 0,1)
    const int r1 = r0 + 8;              // local q row (elems 2,3)
    float gm0 = -INFINITY, gm1 = -INFINITY;
    #pragma unroll
    for (int nt = 0; nt < 5; ++nt) {
        int colb = ng * 40 + nt * 8 + ((lane & 3) << 1);
        #pragma unroll
        for (int u = 0; u < 2; ++u) {
            int col = colb + u;
            int g = lo + col;
            bool okg = ((unsigned)g < SS);
            int j0 = col - r0, j1 = col - r1;
            float v0 = (okg && j0 >= 0 && j0 <= 128) ? sacc[nt][u]   * scale : NEG_INF_F;
            float v1 = (okg && j1 >= 0 && j1 <= 128) ? sacc[nt][2+u] * scale : NEG_INF_F;
            sacc[nt][u]   = v0;
            sacc[nt][2+u] = v1;
            gm0 = fmaxf(gm0, v0);
            gm1 = fmaxf(gm1, v1);
        }
    }
    gm0 = fmaxf(gm0, __shfl_xor_sync(0xffffffffu, gm0, 1));
    gm0 = fmaxf(gm0, __shfl_xor_sync(0xffffffffu, gm0, 2));
    gm1 = fmaxf(gm1, __shfl_xor_sync(0xffffffffu, gm1, 1));
    gm1 = fmaxf(gm1, __shfl_xor_sync(0xffffffffu, gm1, 2));
    float ps0 = 0.f, ps1 = 0.f;
    #pragma unroll
    for (int nt = 0; nt < 5; ++nt) {
        #pragma unroll
        for (int u = 0; u < 2; ++u) {
            float e0 = __expf(sacc[nt][u]   - gm0);
            float e1 = __expf(sacc[nt][2+u] - gm1);
            sacc[nt][u]   = e0;
            sacc[nt][2+u] = e1;
            ps0 += e0;
            ps1 += e1;
        }
    }
    ps0 += __shfl_xor_sync(0xffffffffu, ps0, 1);
    ps0 += __shfl_xor_sync(0xffffffffu, ps0, 2);
    ps1 += __shfl_xor_sync(0xffffffffu, ps1, 1);
    ps1 += __shfl_xor_sync(0xffffffffu, ps1, 2);
    if ((lane & 3) == 0) {
        ((float*)(sb + AT_PMAX))[r0 * 4 + ng] = gm0;
        ((float*)(sb + AT_PMAX))[r1 * 4 + ng] = gm1;
        ((float*)(sb + AT_PSUM))[r0 * 4 + ng] = ps0;
        ((float*)(sb + AT_PSUM))[r1 * 4 + ng] = ps1;
    }
    __syncthreads();   // partials visible; k & q dead

    // ---- load full v tile (LDGs overlap the softmax combine below) ----
    for (int idx = tid; idx < KROWS * 16; idx += 256) {
        int r = idx >> 4, c = idx & 15;
        int gc = min(max(lo + r, 0), SS - 1);
        *(uint4*)(sb + AT_VH + r * 272 + (c << 4)) =
            *(const uint4*)(vh + (size_t)gc * DD + (c << 3));
        *(uint4*)(sb + AT_VL + r * 272 + (c << 4)) =
            *(const uint4*)(vl + (size_t)gc * DD + (c << 3));
    }

    // ---- combine partials -> full softmax; write probs into pt ----
    {
        float4 m40 = *(const float4*)((const float*)(sb + AT_PMAX) + r0 * 4);
        float4 m41 = *(const float4*)((const float*)(sb + AT_PMAX) + r1 * 4);
        float4 s40 = *(const float4*)((const float*)(sb + AT_PSUM) + r0 * 4);
        float4 s41 = *(const float4*)((const float*)(sb + AT_PSUM) + r1 * 4);
        float m0 = fmaxf(fmaxf(m40.x, m40.y), fmaxf(m40.z, m40.w));
        float m1 = fmaxf(fmaxf(m41.x, m41.y), fmaxf(m41.z, m41.w));
        float s0w = s40.x * __expf(m40.x - m0) + s40.y * __expf(m40.y - m0)
                  + s40.z * __expf(m40.z - m0) + s40.w * __expf(m40.w - m0);
        float s1w = s41.x * __expf(m41.x - m1) + s41.y * __expf(m41.y - m1)
                  + s41.z * __expf(m41.z - m1) + s41.w * __expf(m41.w - m1);
        if ((lane & 3) == 0 && ng == 0) {
            ((float*)(sb + AT_WS))[r0] = s0w;
            ((float*)(sb + AT_WS))[r1] = s1w;
        }
        float f0 = __expf(gm0 - m0);
        float f1 = __expf(gm1 - m1);
        #pragma unroll
        for (int nt = 0; nt < 5; ++nt) {
            int cb = (ng * 40 + nt * 8 + ((lane & 3) << 1)) * 2;   // byte offset
            float p00 = sacc[nt][0] * f0, p01 = sacc[nt][1] * f0;
            float p10 = sacc[nt][2] * f1, p11 = sacc[nt][3] * f1;
            *(__nv_bfloat162*)(sb + AT_PTH + r0 * PTST + cb) = split_hi2(p00, p01);
            *(__nv_bfloat162*)(sb + AT_PTL + r0 * PTST + cb) = split_lo2(p00, p01);
            *(__nv_bfloat162*)(sb + AT_PTH + r1 * PTST + cb) = split_hi2(p10, p11);
            *(__nv_bfloat162*)(sb + AT_PTL + r1 * PTST + cb) = split_lo2(p10, p11);
        }
    }
    __syncthreads();

    // ---- P.V MMA: single pass over all 160 k rows ----
    float oacc[4][4];
    #pragma unroll
    for (int nt = 0; nt < 4; ++nt)
        #pragma unroll
        for (int e = 0; e < 4; ++e) oacc[nt][e] = 0.f;

    #pragma unroll
    for (int ks = 0; ks < 10; ++ks) {
        const int abase = (mt * 16 + ar) * PTST + ks * 32 + ac;
        uint32_t phi[4], plo[4];
        phi[0] = *(const uint32_t*)(sb + AT_PTH + abase);
        phi[1] = *(const uint32_t*)(sb + AT_PTH + abase + 8*PTST);
        phi[2] = *(const uint32_t*)(sb + AT_PTH + abase + 16);
        phi[3] = *(const uint32_t*)(sb + AT_PTH + abase + 8*PTST + 16);
        plo[0] = *(const uint32_t*)(sb + AT_PTL + abase);
        plo[1] = *(const uint32_t*)(sb + AT_PTL + abase + 8*PTST);
        plo[2] = *(const uint32_t*)(sb + AT_PTL + abase + 16);
        plo[3] = *(const uint32_t*)(sb + AT_PTL + abase + 8*PTST + 16);
        const uint32_t vrow = sbase + AT_VH + (ks * 16 + (lane & 15)) * 272;
        #pragma unroll
        for (int nt = 0; nt < 4; ++nt) {
            int n0 = ng * 32 + nt * 8;
            uint32_t vhf[2], vlf[2];
            ldmx2t(vhf[0], vhf[1], vrow + n0 * 2);
            ldmx2t(vlf[0], vlf[1], vrow + (AT_VL - AT_VH) + n0 * 2);
            mma16816(oacc[nt], phi, vhf);
            mma16816(oacc[nt], phi, vlf);
            mma16816(oacc[nt], plo, vhf);
        }
    }

    // ---- epilogue: normalize by ws, store ----
    {
        const float* ws = (const float*)(sb + AT_WS);
        float inv0 = 1.0f / ws[r0];
        float inv1 = 1.0f / ws[r1];
        float* op0 = outp + ((size_t)b * SS + s0 + r0) * DD;
        float* op1 = outp + ((size_t)b * SS + s0 + r1) * DD;
        #pragma unroll
        for (int nt = 0; nt < 4; ++nt) {
            int c = ng * 32 + nt * 8 + ((lane & 3) << 1);
            *(float2*)(op0 + c) = make_float2(oacc[nt][0] * inv0, oacc[nt][1] * inv0);
            *(float2*)(op1 + c) = make_float2(oacc[nt][2] * inv1, oacc[nt][3] * inv1);
        }
    }
}

extern "C" void kernel_launch(void* const* d_in, const int* in_sizes, int n_in,
                              void* d_out, int out_size)
{
    const float* x  = (const float*)d_in[0];
    const float* Wq = (const float*)d_in[1];
    const float* bq = (const float*)d_in[2];
    const float* Wk = (const float*)d_in[3];
    const float* bk = (const float*)d_in[4];
    const float* Wv = (const float*)d_in[5];
    const float* bv = (const float*)d_in[6];
    float* out = (float*)d_out;

    cudaFuncSetAttribute(qkv_mma_kernel,
                         cudaFuncAttributeMaxDynamicSharedMemorySize, QKV_SMEM);
    cudaFuncSetAttribute(attn_kernel,
                         cudaFuncAttributeMaxDynamicSharedMemorySize, ATTN_SMEM);

    wconv_kernel<<<dim3(3, 16), 256>>>(Wq, Wk, Wv);
    qkv_mma_kernel<<<BB * SS / 64, 256, QKV_SMEM>>>(x, bq, bk, bv);
    attn_kernel<<<BB * SS / TQ, 256, ATTN_SMEM>>>(out);
}